// round 14
// baseline (speedup 1.0000x reference)
#include <cuda_runtime.h>
#include <cstdint>

// PNN_62156766707845 — GB300 sm_103a, round 14
// R13 + MTILE=32 / 128-thread CTAs / 5 CTAs per SM target.
// More independent barrier domains -> staggered gather bursts -> higher DRAM busy.
// Pipeline: Xi@i+4, emb@i+3, cvt+store@i+2, compute@i; 4-buffer ring.

#define FDIM   39
#define EDIM   16
#define VDIM   100000
#define MTILE  32
#define NTHR   128
#define NCHUNK 10
#define FPC    4
#define NBUF   4

#define RSU     80                   // A row stride in u32 (320B)
#define BUF_U   (MTILE * RSU)        // 2560 u32 = 10KB per buffer
#define SMEM_BYTES (NBUF * BUF_U * 4)   // 40KB
#define XS_S    66

// B fragments packed: [chunk][ktg][ngroup][lane] = {h0, h1, l0, l1}
__device__ uint4 Bfrag4[NCHUNK][FPC][8][32];

__device__ __forceinline__ uint32_t packbf(float lo, float hi) {
    uint32_t r;
    asm("cvt.rn.bf16x2.f32 %0, %1, %2;" : "=r"(r) : "f"(hi), "f"(lo));
    return r;
}
__device__ __forceinline__ float f_lo(uint32_t u) { return __uint_as_float(u << 16); }
__device__ __forceinline__ float f_hi(uint32_t u) { return __uint_as_float(u & 0xFFFF0000u); }

__device__ __forceinline__ void mma16(float* c, const uint32_t* a, const uint32_t* b) {
    asm volatile(
        "mma.sync.aligned.m16n8k16.row.col.f32.bf16.bf16.f32 "
        "{%0,%1,%2,%3}, {%4,%5,%6,%7}, {%8,%9}, {%0,%1,%2,%3};"
        : "+f"(c[0]), "+f"(c[1]), "+f"(c[2]), "+f"(c[3])
        : "r"(a[0]), "r"(a[1]), "r"(a[2]), "r"(a[3]), "r"(b[0]), "r"(b[1]));
}

__device__ __forceinline__ int rsz(int r) { return ((r >> 1) & 1) * 4; }

__device__ __forceinline__ void cvt4_store_i(uint32_t* rowp,
                                             float x0, float x1, float x2, float x3,
                                             int posA) {
    uint32_t h0 = packbf(x0, x1);
    uint32_t h1 = packbf(x2, x3);
    uint32_t l0 = packbf(x0 - f_lo(h0), x1 - f_hi(h0));
    uint32_t l1 = packbf(x2 - f_lo(h1), x3 - f_hi(h1));
    *(uint2*)(rowp + 2 * posA)     = make_uint2(h0, l0);
    *(uint2*)(rowp + 2 * posA + 4) = make_uint2(h1, l1);
}

// ---- B prep kernel ----
extern "C" __global__ void prep_b_kernel(const float* __restrict__ w_first,
                                         const float* __restrict__ w_inner)
{
    int t = blockIdx.x * blockDim.x + threadIdx.x;
    if (t >= NCHUNK * FPC * 8 * 32) return;
    const int lane = t & 31;
    const int qr = lane >> 2, qc = lane & 3;
    const int ng  = (t >> 5) & 7;
    const int ktg = (t >> 8) & 3;
    const int c   = t >> 10;
    const int n = ng * 8 + qr;
    const int f = c * FPC + ktg;
    float v0 = 0.f, v1 = 0.f, v2 = 0.f, v3 = 0.f;
    if (f < FDIM) {
        const float* src = (n < 32)
            ? (w_first + ((long long)n * FDIM + f) * EDIM)
            : (w_inner + ((long long)(n - 32) * FDIM + f) * EDIM);
        v0 = src[2 * qc];     v1 = src[2 * qc + 1];
        v2 = src[2 * qc + 8]; v3 = src[2 * qc + 9];
    }
    uint32_t h0 = packbf(v0, v1), h1 = packbf(v2, v3);
    uint32_t l0 = packbf(v0 - f_lo(h0), v1 - f_hi(h0));
    uint32_t l1 = packbf(v2 - f_lo(h1), v3 - f_hi(h1));
    Bfrag4[c][ktg][ng][lane] = make_uint4(h0, h1, l0, l1);
}

extern "C" __global__ void __launch_bounds__(NTHR, 5)
pnn_kernel(const int* __restrict__ Xi, const float* __restrict__ Xv,
           const float* __restrict__ emb,
           const float* __restrict__ lin1W, const float* __restrict__ lin1b,
           const float* __restrict__ lin2W, const float* __restrict__ lin2b,
           const float* __restrict__ lastW, const float* __restrict__ lastb,
           float* __restrict__ out, int B)
{
    extern __shared__ float sm[];
    uint32_t* smu = (uint32_t*)sm;

    const int tid  = threadIdx.x;
    const int wid  = tid >> 5;
    const int lane = tid & 31;
    const int qr   = lane >> 2;
    const int qc   = lane & 3;
    const int RM   = (wid >> 1) * 16;     // warp M base: 0/16
    const int CN   = (wid & 1) * 32;      // warp N base: 0/32
    const int NG0  = CN >> 3;

    // A staging role: thread = (row 0..31, quarter 0..3)
    const int row  = tid >> 2;
    const int q    = tid & 3;
    const int posA = (q < 2) ? 4 * q : 4 * q - 7;
    const int rowoff = row * RSU + rsz(row);
    const int grow = blockIdx.x * MTILE + row;
    const long long rowbase = (long long)((grow < B) ? grow : 0) * FDIM;

    float pf[FPC][4]; float pxv[FPC];
    int   xi[FPC];    float xvr[FPC];

    // ---- prologue: stage chunks 0,1; emb chunk 2 -> pf; Xi chunk 3 -> xi ----
#pragma unroll
    for (int s = 0; s < FPC; s++) {
        int idx = Xi[rowbase + s];
        float xv = Xv[rowbase + s];
        float4 v = *((const float4*)emb + ((long long)s * VDIM + idx) * 4 + q);
        cvt4_store_i(smu + rowoff + s * 16,
                     v.x * xv, v.y * xv, v.z * xv, v.w * xv, posA);

        const int f1 = FPC + s;
        idx = Xi[rowbase + f1];
        xv  = Xv[rowbase + f1];
        v = *((const float4*)emb + ((long long)f1 * VDIM + idx) * 4 + q);
        cvt4_store_i(smu + BUF_U + rowoff + s * 16,
                     v.x * xv, v.y * xv, v.z * xv, v.w * xv, posA);

        const int f2 = 2 * FPC + s;
        idx = Xi[rowbase + f2];
        pxv[s] = Xv[rowbase + f2];
        v = *((const float4*)emb + ((long long)f2 * VDIM + idx) * 4 + q);
        pf[s][0] = v.x; pf[s][1] = v.y; pf[s][2] = v.z; pf[s][3] = v.w;

        const int f3 = 3 * FPC + s;
        xi[s]  = Xi[rowbase + f3];
        xvr[s] = Xv[rowbase + f3];
    }
    __syncthreads();

    float acc[4][4];
#pragma unroll
    for (int nt = 0; nt < 4; nt++)
#pragma unroll
        for (int c = 0; c < 4; c++) acc[nt][c] = 0.f;

    // consumer row offsets (u32)
    const int ra = RM + qr;
    const int rb = ra + 8;
    const int raoff = ra * RSU + rsz(ra);
    const int rboff = rb * RSU + rsz(rb);

    for (int i = 0; i < NCHUNK; i++) {
        // 1) cvt+store chunk i+2 from pf into buf (i+2)%NBUF
        if (i + 2 < NCHUNK) {
            uint32_t* base = smu + ((i + 2) & (NBUF - 1)) * BUF_U + rowoff;
#pragma unroll
            for (int s = 0; s < FPC; s++)
                cvt4_store_i(base + s * 16,
                             pf[s][0] * pxv[s], pf[s][1] * pxv[s],
                             pf[s][2] * pxv[s], pf[s][3] * pxv[s], posA);
        }
        // 2) emb LDG chunk i+3 using resident indices
        if (i + 3 < NCHUNK) {
#pragma unroll
            for (int s = 0; s < FPC; s++) {
                const int f = FPC * (i + 3) + s;
                if (f < FDIM) {
                    pxv[s] = xvr[s];
                    float4 v = *((const float4*)emb + ((long long)f * VDIM + xi[s]) * 4 + q);
                    pf[s][0] = v.x; pf[s][1] = v.y; pf[s][2] = v.z; pf[s][3] = v.w;
                } else {
                    pxv[s] = 0.f;
                    pf[s][0] = pf[s][1] = pf[s][2] = pf[s][3] = 0.f;
                }
            }
        }
        // 3) Xi/Xv chunk i+4
        if (i + 4 < NCHUNK) {
#pragma unroll
            for (int s = 0; s < FPC; s++) {
                const int f = FPC * (i + 4) + s;
                if (f < FDIM) {
                    xi[s]  = Xi[rowbase + f];
                    xvr[s] = Xv[rowbase + f];
                } else { xi[s] = 0; xvr[s] = 0.f; }
            }
        }

        // 4) compute chunk i from buf i%NBUF; B frags double-buffered per ktg
        {
            const uint32_t* base = smu + (i & (NBUF - 1)) * BUF_U;
            uint4 bcur[4], bnxt[4];
#pragma unroll
            for (int nt = 0; nt < 4; nt++)
                bcur[nt] = Bfrag4[i][0][NG0 + nt][lane];
#pragma unroll
            for (int ktg = 0; ktg < FPC; ktg++) {
                if (ktg < FPC - 1) {
#pragma unroll
                    for (int nt = 0; nt < 4; nt++)
                        bnxt[nt] = Bfrag4[i][ktg + 1][NG0 + nt][lane];
                }
                const int co = ktg * 16 + 4 * qc;
                uint4 ua = *(const uint4*)(base + raoff + co);
                uint4 ub = *(const uint4*)(base + rboff + co);
                uint32_t ah[4] = { ua.x, ub.x, ua.z, ub.z };
                uint32_t al[4] = { ua.y, ub.y, ua.w, ub.w };
#pragma unroll
                for (int nt = 0; nt < 4; nt++) {
                    const uint32_t bh[2] = { bcur[nt].x, bcur[nt].y };
                    mma16(acc[nt], ah, bh);
                }
#pragma unroll
                for (int nt = 0; nt < 4; nt++) {
                    const uint32_t bl[2] = { bcur[nt].z, bcur[nt].w };
                    mma16(acc[nt], ah, bl);
                }
#pragma unroll
                for (int nt = 0; nt < 4; nt++) {
                    const uint32_t bh[2] = { bcur[nt].x, bcur[nt].y };
                    mma16(acc[nt], al, bh);
                }
#pragma unroll
                for (int nt = 0; nt < 4; nt++) bcur[nt] = bnxt[nt];
            }
        }
        // barrier every 2 iterations (RAW at +2, WAR at -2)
        if (i & 1) __syncthreads();
    }

    // ---- epilogue: write D, then MLP (no k-split combine needed) ----
    float* xs  = sm;                 // [32][66] = 2112 floats
    float* l1  = sm + 2112;
    float* l2  = l1 + 1024;
    float* bb1 = l2 + 1024;
    float* bb2 = bb1 + 32;
    float* lw  = bb2 + 32;
    float* lb  = lw + 32;

    for (int i = tid; i < 1024; i += NTHR) { l1[i] = lin1W[i]; l2[i] = lin2W[i]; }
    if (tid < 32) { bb1[tid] = lin1b[tid]; bb2[tid] = lin2b[tid]; lw[tid] = lastW[tid]; }
    if (tid == 0) lb[0] = lastb[0];

    {
        const int r0 = RM + qr;
#pragma unroll
        for (int nt = 0; nt < 4; nt++) {
            const int n = CN + nt * 8 + 2 * qc;
            *(float2*)(xs + r0 * XS_S + n)       = make_float2(acc[nt][0], acc[nt][1]);
            *(float2*)(xs + (r0 + 8) * XS_S + n) = make_float2(acc[nt][2], acc[nt][3]);
        }
    }
    __syncthreads();

    // MLP: 2 threads per row (threads 0..63)
    if (tid < 2 * MTILE) {
        const int rr = tid >> 1;
        const int half = tid & 1;
        float* xr = xs + rr * XS_S;

        float x[32];
#pragma unroll
        for (int d = 0; d < 32; d++) {
            float s = xr[32 + d];
            x[d] = fmaf(s, s, xr[d]);
        }
        __syncwarp();

        float h[16];
#pragma unroll
        for (int jl = 0; jl < 16; jl++) {
            const int j = half * 16 + jl;
            float a = bb1[j];
            const float* wrow = l1 + j * 32;
#pragma unroll
            for (int d = 0; d < 32; d++) a = fmaf(wrow[d], x[d], a);
            h[jl] = fmaxf(a, 0.0f);
        }
        __syncwarp();
#pragma unroll
        for (int jl = 0; jl < 16; jl++) xr[half * 16 + jl] = h[jl];
        __syncwarp();

        float h1[32];
#pragma unroll
        for (int d = 0; d < 32; d++) h1[d] = xr[d];

        float h2[16];
#pragma unroll
        for (int jl = 0; jl < 16; jl++) {
            const int j = half * 16 + jl;
            float a = bb2[j];
            const float* wrow = l2 + j * 32;
#pragma unroll
            for (int d = 0; d < 32; d++) a = fmaf(wrow[d], h1[d], a);
            h2[jl] = fmaxf(a, 0.0f);
        }
        __syncwarp();
#pragma unroll
        for (int jl = 0; jl < 16; jl++) xr[half * 16 + jl] = h2[jl];
        __syncwarp();

        if (half == 0) {
            const int g = blockIdx.x * MTILE + rr;
            if (g < B) {
                float a = lb[0];
#pragma unroll
                for (int j = 0; j < 32; j++) a = fmaf(lw[j], xr[j], a);
                out[g] = a;
            }
        }
    }
}

extern "C" void kernel_launch(void* const* d_in, const int* in_sizes, int n_in,
                              void* d_out, int out_size)
{
    const int*   Xi      = (const int*)d_in[0];
    const float* Xv      = (const float*)d_in[1];
    const float* emb     = (const float*)d_in[2];
    const float* w_first = (const float*)d_in[3];
    const float* w_inner = (const float*)d_in[4];
    const float* lin1W   = (const float*)d_in[5];
    const float* lin1b   = (const float*)d_in[6];
    const float* lin2W   = (const float*)d_in[7];
    const float* lin2b   = (const float*)d_in[8];
    const float* lastW   = (const float*)d_in[9];
    const float* lastb   = (const float*)d_in[10];
    float* out = (float*)d_out;

    const int B = in_sizes[0] / FDIM;

    prep_b_kernel<<<40, 256>>>(w_first, w_inner);

    cudaFuncSetAttribute(pnn_kernel, cudaFuncAttributeMaxDynamicSharedMemorySize,
                         SMEM_BYTES);
    const int grid = (B + MTILE - 1) / MTILE;
    pnn_kernel<<<grid, NTHR, SMEM_BYTES>>>(Xi, Xv, emb,
                                           lin1W, lin1b, lin2W, lin2b,
                                           lastW, lastb, out, B);
}

// round 15
// speedup vs baseline: 1.2708x; 1.2708x over previous
#include <cuda_runtime.h>
#include <cstdint>

// PNN_62156766707845 — GB300 sm_103a, round 15
// Warp-specialized: 4 producer warps (gather/cvt/store) + 4 consumer warps
// (full-K mma per 32x32 quadrant). Named-barrier FULL/EMPTY per ring slot.
// bf16 2-term split, m16n8k16, B fragments precomputed (prep kernel).

#define FDIM   39
#define EDIM   16
#define VDIM   100000
#define MTILE  64
#define NTHR   256
#define NCHUNK 10
#define FPC    4
#define NBUF   4

#define RSU     80                       // A row stride in u32 (320B)
#define BUF_U   (64 * RSU)               // 5120 u32 = 20KB per slot
#define SMEM_BYTES (NBUF * BUF_U * 4)    // 80KB
#define XS_S    66

__device__ uint4 Bfrag4[NCHUNK][FPC][8][32];

__device__ __forceinline__ uint32_t packbf(float lo, float hi) {
    uint32_t r;
    asm("cvt.rn.bf16x2.f32 %0, %1, %2;" : "=r"(r) : "f"(hi), "f"(lo));
    return r;
}
__device__ __forceinline__ float f_lo(uint32_t u) { return __uint_as_float(u << 16); }
__device__ __forceinline__ float f_hi(uint32_t u) { return __uint_as_float(u & 0xFFFF0000u); }

__device__ __forceinline__ void mma16(float* c, const uint32_t* a, const uint32_t* b) {
    asm volatile(
        "mma.sync.aligned.m16n8k16.row.col.f32.bf16.bf16.f32 "
        "{%0,%1,%2,%3}, {%4,%5,%6,%7}, {%8,%9}, {%0,%1,%2,%3};"
        : "+f"(c[0]), "+f"(c[1]), "+f"(c[2]), "+f"(c[3])
        : "r"(a[0]), "r"(a[1]), "r"(a[2]), "r"(a[3]), "r"(b[0]), "r"(b[1]));
}

// swizzle: distinct banks for 16-row producer STS phases AND consumer LDS.128
__device__ __forceinline__ int rsz(int r) {
    return ((r >> 1) & 1) * 4 + ((r >> 2) & 1) * 8;
}

__device__ __forceinline__ void bar_sync(int id) {
    asm volatile("bar.sync %0, %1;" :: "r"(id), "r"(256) : "memory");
}
__device__ __forceinline__ void bar_arrive(int id) {
    asm volatile("bar.arrive %0, %1;" :: "r"(id), "r"(256) : "memory");
}

__device__ __forceinline__ void cvt4_store_i(uint32_t* rowp,
                                             float x0, float x1, float x2, float x3,
                                             int posA) {
    uint32_t h0 = packbf(x0, x1);
    uint32_t h1 = packbf(x2, x3);
    uint32_t l0 = packbf(x0 - f_lo(h0), x1 - f_hi(h0));
    uint32_t l1 = packbf(x2 - f_lo(h1), x3 - f_hi(h1));
    *(uint2*)(rowp + 2 * posA)     = make_uint2(h0, l0);
    *(uint2*)(rowp + 2 * posA + 4) = make_uint2(h1, l1);
}

extern "C" __global__ void prep_b_kernel(const float* __restrict__ w_first,
                                         const float* __restrict__ w_inner)
{
    int t = blockIdx.x * blockDim.x + threadIdx.x;
    if (t >= NCHUNK * FPC * 8 * 32) return;
    const int lane = t & 31;
    const int qr = lane >> 2, qc = lane & 3;
    const int ng  = (t >> 5) & 7;
    const int ktg = (t >> 8) & 3;
    const int c   = t >> 10;
    const int n = ng * 8 + qr;
    const int f = c * FPC + ktg;
    float v0 = 0.f, v1 = 0.f, v2 = 0.f, v3 = 0.f;
    if (f < FDIM) {
        const float* src = (n < 32)
            ? (w_first + ((long long)n * FDIM + f) * EDIM)
            : (w_inner + ((long long)(n - 32) * FDIM + f) * EDIM);
        v0 = src[2 * qc];     v1 = src[2 * qc + 1];
        v2 = src[2 * qc + 8]; v3 = src[2 * qc + 9];
    }
    uint32_t h0 = packbf(v0, v1), h1 = packbf(v2, v3);
    uint32_t l0 = packbf(v0 - f_lo(h0), v1 - f_hi(h0));
    uint32_t l1 = packbf(v2 - f_lo(h1), v3 - f_hi(h1));
    Bfrag4[c][ktg][ng][lane] = make_uint4(h0, h1, l0, l1);
}

extern "C" __global__ void __launch_bounds__(NTHR, 2)
pnn_kernel(const int* __restrict__ Xi, const float* __restrict__ Xv,
           const float* __restrict__ emb,
           const float* __restrict__ lin1W, const float* __restrict__ lin1b,
           const float* __restrict__ lin2W, const float* __restrict__ lin2b,
           const float* __restrict__ lastW, const float* __restrict__ lastb,
           float* __restrict__ out, int B)
{
    extern __shared__ float sm[];
    uint32_t* smu = (uint32_t*)sm;

    const int tid  = threadIdx.x;
    const int wid  = tid >> 5;
    const int lane = tid & 31;
    const int qr   = lane >> 2;
    const int qc   = lane & 3;
    const bool producer = (wid < 4);

    float acc[2][4][4];
#pragma unroll
    for (int mt = 0; mt < 2; mt++)
#pragma unroll
        for (int nt = 0; nt < 4; nt++)
#pragma unroll
            for (int c = 0; c < 4; c++) acc[mt][nt][c] = 0.f;

    if (producer) {
        // ---- producer: thread -> (row = tid>>1, q pair = (tid&1)*2, +1) ----
        const int row   = tid >> 1;
        const int qbase = (tid & 1) * 2;
        const int rowoff = row * RSU + rsz(row);
        const int grow = blockIdx.x * MTILE + row;
        const long long rowbase = (long long)((grow < B) ? grow : 0) * FDIM;
        // posA for qbase and qbase+1
        const int posA0 = (qbase < 2) ? 4 * qbase : 4 * qbase - 7;
        const int posA1 = (qbase + 1 < 2) ? 4 * (qbase + 1) : 4 * (qbase + 1) - 7;

        float pf[FPC][2][4];    // [feature][qsel][4]
        float pxv[FPC];
        int   xi[FPC]; float xvr[FPC];

        // prologue: Xi chunk0 -> xi; emb chunk0 -> pf; Xi chunk1 -> xi
#pragma unroll
        for (int s = 0; s < FPC; s++) { xi[s] = Xi[rowbase + s]; xvr[s] = Xv[rowbase + s]; }
#pragma unroll
        for (int s = 0; s < FPC; s++) {
            const float4* p = (const float4*)emb + ((long long)s * VDIM + xi[s]) * 4 + qbase;
            *(float4*)pf[s][0] = p[0];
            *(float4*)pf[s][1] = p[1];
            pxv[s] = xvr[s];
        }
#pragma unroll
        for (int s = 0; s < FPC; s++) {
            xi[s] = Xi[rowbase + FPC + s];
            xvr[s] = Xv[rowbase + FPC + s];
        }

        for (int c = 0; c < NCHUNK; c++) {
            const int slot = c & (NBUF - 1);
            if (c >= NBUF) bar_sync(5 + slot);            // EMPTY wait
            uint32_t* base = smu + slot * BUF_U + rowoff;
#pragma unroll
            for (int s = 0; s < FPC; s++) {
                float xv = pxv[s];
                cvt4_store_i(base + s * 16,
                             pf[s][0][0] * xv, pf[s][0][1] * xv,
                             pf[s][0][2] * xv, pf[s][0][3] * xv, posA0);
                cvt4_store_i(base + s * 16,
                             pf[s][1][0] * xv, pf[s][1][1] * xv,
                             pf[s][1][2] * xv, pf[s][1][3] * xv, posA1);
            }
            bar_arrive(1 + slot);                         // FULL arrive
            // emb LDG chunk c+1 (indices resident)
            if (c + 1 < NCHUNK) {
#pragma unroll
                for (int s = 0; s < FPC; s++) {
                    const int f = FPC * (c + 1) + s;
                    if (f < FDIM) {
                        const float4* p = (const float4*)emb +
                                          ((long long)f * VDIM + xi[s]) * 4 + qbase;
                        *(float4*)pf[s][0] = p[0];
                        *(float4*)pf[s][1] = p[1];
                        pxv[s] = xvr[s];
                    } else {
                        pxv[s] = 0.f;
#pragma unroll
                        for (int j = 0; j < 4; j++) { pf[s][0][j] = 0.f; pf[s][1][j] = 0.f; }
                    }
                }
            }
            // Xi/Xv chunk c+2
            if (c + 2 < NCHUNK) {
#pragma unroll
                for (int s = 0; s < FPC; s++) {
                    const int f = FPC * (c + 2) + s;
                    if (f < FDIM) { xi[s] = Xi[rowbase + f]; xvr[s] = Xv[rowbase + f]; }
                    else          { xi[s] = 0; xvr[s] = 0.f; }
                }
            }
        }
    } else {
        // ---- consumer: warp tq = wid-4 -> quadrant; full K ----
        const int tq = wid - 4;
        const int RM = (tq & 1) * 32;
        const int CN = (tq >> 1) * 32;
        const int NG0 = CN >> 3;
        int raoff[2], rboff[2];
#pragma unroll
        for (int mt = 0; mt < 2; mt++) {
            const int ra = RM + mt * 16 + qr;
            const int rb = ra + 8;
            raoff[mt] = ra * RSU + rsz(ra);
            rboff[mt] = rb * RSU + rsz(rb);
        }

        for (int c = 0; c < NCHUNK; c++) {
            const int slot = c & (NBUF - 1);
            bar_sync(1 + slot);                           // FULL wait
            const uint32_t* base = smu + slot * BUF_U;
#pragma unroll
            for (int ktg = 0; ktg < FPC; ktg++) {
                uint4 bf[4];
#pragma unroll
                for (int nt = 0; nt < 4; nt++)
                    bf[nt] = Bfrag4[c][ktg][NG0 + nt][lane];
                const int co = ktg * 16 + 4 * qc;
                uint32_t ah[2][4], al[2][4];
#pragma unroll
                for (int mt = 0; mt < 2; mt++) {
                    uint4 ua = *(const uint4*)(base + raoff[mt] + co);
                    uint4 ub = *(const uint4*)(base + rboff[mt] + co);
                    ah[mt][0] = ua.x; ah[mt][1] = ub.x; ah[mt][2] = ua.z; ah[mt][3] = ub.z;
                    al[mt][0] = ua.y; al[mt][1] = ub.y; al[mt][2] = ua.w; al[mt][3] = ub.w;
                }
#pragma unroll
                for (int nt = 0; nt < 4; nt++) {
                    const uint32_t bh[2] = { bf[nt].x, bf[nt].y };
                    mma16(acc[0][nt], ah[0], bh);
                    mma16(acc[1][nt], ah[1], bh);
                }
#pragma unroll
                for (int nt = 0; nt < 4; nt++) {
                    const uint32_t bl[2] = { bf[nt].z, bf[nt].w };
                    mma16(acc[0][nt], ah[0], bl);
                    mma16(acc[1][nt], ah[1], bl);
                }
#pragma unroll
                for (int nt = 0; nt < 4; nt++) {
                    const uint32_t bh[2] = { bf[nt].x, bf[nt].y };
                    mma16(acc[0][nt], al[0], bh);
                    mma16(acc[1][nt], al[1], bh);
                }
            }
            if (c + NBUF < NCHUNK) bar_arrive(5 + slot);  // EMPTY arrive
        }
    }
    __syncthreads();

    // ---- epilogue: consumers write D; then MLP (same as R13) ----
    float* xs  = sm;
    float* l1  = sm + 4224;
    float* l2  = l1 + 1024;
    float* bb1 = l2 + 1024;
    float* bb2 = bb1 + 32;
    float* lw  = bb2 + 32;
    float* lb  = lw + 32;

    for (int i = tid; i < 1024; i += NTHR) { l1[i] = lin1W[i]; l2[i] = lin2W[i]; }
    if (tid < 32) { bb1[tid] = lin1b[tid]; bb2[tid] = lin2b[tid]; lw[tid] = lastW[tid]; }
    if (tid == 0) lb[0] = lastb[0];

    if (!producer) {
        const int tq = wid - 4;
        const int RM = (tq & 1) * 32;
        const int CN = (tq >> 1) * 32;
#pragma unroll
        for (int mt = 0; mt < 2; mt++) {
            const int r0 = RM + mt * 16 + qr;
#pragma unroll
            for (int nt = 0; nt < 4; nt++) {
                const int n = CN + nt * 8 + 2 * qc;
                *(float2*)(xs + r0 * XS_S + n)       = make_float2(acc[mt][nt][0], acc[mt][nt][1]);
                *(float2*)(xs + (r0 + 8) * XS_S + n) = make_float2(acc[mt][nt][2], acc[mt][nt][3]);
            }
        }
    }
    __syncthreads();

    if (tid < 2 * MTILE) {
        const int rr = tid >> 1;
        const int half = tid & 1;
        float* xr = xs + rr * XS_S;

        float x[32];
#pragma unroll
        for (int d = 0; d < 32; d++) {
            float s = xr[32 + d];
            x[d] = fmaf(s, s, xr[d]);
        }
        __syncwarp();

        float h[16];
#pragma unroll
        for (int jl = 0; jl < 16; jl++) {
            const int j = half * 16 + jl;
            float a = bb1[j];
            const float* wrow = l1 + j * 32;
#pragma unroll
            for (int d = 0; d < 32; d++) a = fmaf(wrow[d], x[d], a);
            h[jl] = fmaxf(a, 0.0f);
        }
        __syncwarp();
#pragma unroll
        for (int jl = 0; jl < 16; jl++) xr[half * 16 + jl] = h[jl];
        __syncwarp();

        float h1[32];
#pragma unroll
        for (int d = 0; d < 32; d++) h1[d] = xr[d];

        float h2[16];
#pragma unroll
        for (int jl = 0; jl < 16; jl++) {
            const int j = half * 16 + jl;
            float a = bb2[j];
            const float* wrow = l2 + j * 32;
#pragma unroll
            for (int d = 0; d < 32; d++) a = fmaf(wrow[d], h1[d], a);
            h2[jl] = fmaxf(a, 0.0f);
        }
        __syncwarp();
#pragma unroll
        for (int jl = 0; jl < 16; jl++) xr[half * 16 + jl] = h2[jl];
        __syncwarp();

        if (half == 0) {
            const int g = blockIdx.x * MTILE + rr;
            if (g < B) {
                float a = lb[0];
#pragma unroll
                for (int j = 0; j < 32; j++) a = fmaf(lw[j], xr[j], a);
                out[g] = a;
            }
        }
    }
}

extern "C" void kernel_launch(void* const* d_in, const int* in_sizes, int n_in,
                              void* d_out, int out_size)
{
    const int*   Xi      = (const int*)d_in[0];
    const float* Xv      = (const float*)d_in[1];
    const float* emb     = (const float*)d_in[2];
    const float* w_first = (const float*)d_in[3];
    const float* w_inner = (const float*)d_in[4];
    const float* lin1W   = (const float*)d_in[5];
    const float* lin1b   = (const float*)d_in[6];
    const float* lin2W   = (const float*)d_in[7];
    const float* lin2b   = (const float*)d_in[8];
    const float* lastW   = (const float*)d_in[9];
    const float* lastb   = (const float*)d_in[10];
    float* out = (float*)d_out;

    const int B = in_sizes[0] / FDIM;

    prep_b_kernel<<<40, 256>>>(w_first, w_inner);

    cudaFuncSetAttribute(pnn_kernel, cudaFuncAttributeMaxDynamicSharedMemorySize,
                         SMEM_BYTES);
    const int grid = (B + MTILE - 1) / MTILE;
    pnn_kernel<<<grid, NTHR, SMEM_BYTES>>>(Xi, Xv, emb,
                                           lin1W, lin1b, lin2W, lin2b,
                                           lastW, lastb, out, B);
}